// round 1
// baseline (speedup 1.0000x reference)
#include <cuda_runtime.h>
#include <cuda_bf16.h>
#include <math.h>

// ---------------- problem constants ----------------
#define NN      65536
#define BATCH   4
#define CH      4
#define ROWS    16      // BATCH*CH
#define JLEV    5
#define QQ      8
#define CQ      32      // QQ*CH
#define TT      15
#define OUTN    16384   // NN/4
#define OUTCH   160     // JLEV*CQ

// ---------------- wavelet filters ----------------
__constant__ float c_H0O[13] = {
  -0.00455690456024f, -0.00543947593727f,  0.01702522388155f,  0.02382538479492f,
  -0.10671180468666f,  0.01186609203379f,  0.56881042071212f,  0.75614564389252f,
   0.27529538466888f, -0.11720388769911f, -0.03887280126882f,  0.03466034684485f,
  -0.00388321199915f };
// H1O[k] = (-1)^k * H0O[12-k]
__constant__ float c_H1O[13] = {
  -0.00388321199915f, -0.03466034684485f, -0.03887280126882f,  0.11720388769911f,
   0.27529538466888f, -0.75614564389252f,  0.56881042071212f, -0.01186609203379f,
  -0.10671180468666f, -0.02382538479492f,  0.01702522388155f,  0.00543947593727f,
  -0.00455690456024f };
__constant__ float c_H0A[10] = {
   0.03516384f, 0.0f, -0.08832942f, 0.23389032f, 0.76027237f,
   0.58751830f, 0.0f, -0.11430184f, 0.0f, 0.0f };
__constant__ float c_H0B[10] = {
   0.0f, 0.0f, -0.11430184f, 0.0f, 0.58751830f,
   0.76027237f, 0.23389032f, -0.08832942f, 0.0f, 0.03516384f };
// H1A[k] = (-1)^k * H0B[k]
__constant__ float c_H1A[10] = {
   0.0f, 0.0f, -0.11430184f, 0.0f, 0.58751830f,
  -0.76027237f, 0.23389032f, 0.08832942f, 0.0f, -0.03516384f };
// H1B = reverse(H1A)
__constant__ float c_H1B[10] = {
  -0.03516384f, 0.0f, 0.08832942f, 0.23389032f, -0.76027237f,
   0.58751830f, 0.0f, -0.11430184f, 0.0f, 0.0f };

// ---------------- scratch (bandpass outputs of the UDTCWT) ----------------
__device__ float g_bpr[(size_t)JLEV * ROWS * NN];
__device__ float g_bpi[(size_t)JLEV * ROWS * NN];

// ---------------- kernel 1: undecimated dual-tree CWT ----------------
#define TILE_W 2048
#define HALO   80
#define EXT    (TILE_W + 2*HALO)   // 2208

// One level of the dual tree (levels >= 1): bandpass (central TILE_W samples,
// written to global) + the two lowpass chains (computed with margin M).
template<int D, int M>
__device__ __forceinline__ void tree_level(
    const float* la, const float* lb,
    float* la_n, float* lb_n,
    float* __restrict__ bpr, float* __restrict__ bpi)
{
  const int PAD = (D * 9) / 2;
  for (int i = threadIdx.x; i < TILE_W; i += 256) {
    const int s = HALO + i;
    float ar = 0.f, ai = 0.f;
#pragma unroll
    for (int k = 0; k < 10; k++) {
      ar = fmaf(c_H1A[k], la[s + D*k - PAD], ar);
      ai = fmaf(c_H1B[k], lb[s + D*k - PAD], ai);
    }
    bpr[i] = ar; bpi[i] = ai;
  }
  if (la_n != nullptr) {
    for (int i = threadIdx.x; i < TILE_W + 2*M; i += 256) {
      const int s = HALO - M + i;
      float a = 0.f, b = 0.f;
#pragma unroll
      for (int k = 0; k < 10; k++) {
        a = fmaf(c_H0A[k], la[s + D*k - PAD], a);
        b = fmaf(c_H0B[k], lb[s + D*k - PAD], b);
      }
      la_n[s] = a; lb_n[s] = b;
    }
  }
}

__global__ __launch_bounds__(256) void udtcwt_kernel(const float* __restrict__ x)
{
  __shared__ float sA[EXT], sB[EXT], sC[EXT], sD[EXT];
  const int row = blockIdx.y;
  const int t0  = blockIdx.x * TILE_W;
  const float* xr = x + (size_t)row * NN;

  // load tile + halo, zero outside the row
  for (int s = threadIdx.x; s < EXT; s += 256) {
    const int g = t0 - HALO + s;
    sA[s] = (g >= 0 && g < NN) ? xr[g] : 0.f;
  }
  __syncthreads();

  // ---- level 0 (13-tap near_sym_b, d=1, pad 6). Both trees identical. ----
  {
    float* outr = g_bpr + ((size_t)(0*ROWS + row)) * NN + t0;
    float* outi = g_bpi + ((size_t)(0*ROWS + row)) * NN + t0;
    for (int i = threadIdx.x; i < TILE_W; i += 256) {
      const int s = HALO + i;
      float acc = 0.f;
#pragma unroll
      for (int k = 0; k < 13; k++) acc = fmaf(c_H1O[k], sA[s + k - 6], acc);
      outr[i] = acc; outi[i] = acc;
    }
    for (int i = threadIdx.x; i < TILE_W + 2*68; i += 256) {
      const int s = HALO - 68 + i;
      float acc = 0.f;
#pragma unroll
      for (int k = 0; k < 13; k++) acc = fmaf(c_H0O[k], sA[s + k - 6], acc);
      sB[s] = acc;   // L (la == lb after level 0)
    }
  }
  __syncthreads();

  // ---- level 1: d=1, qshift filters, trees diverge ----
  tree_level<1, 63>(sB, sB, sC, sD,
      g_bpr + ((size_t)(1*ROWS + row))*NN + t0,
      g_bpi + ((size_t)(1*ROWS + row))*NN + t0);
  __syncthreads();
  // ---- level 2: d=2 ----
  tree_level<2, 54>(sC, sD, sA, sB,
      g_bpr + ((size_t)(2*ROWS + row))*NN + t0,
      g_bpi + ((size_t)(2*ROWS + row))*NN + t0);
  __syncthreads();
  // ---- level 3: d=4 ----
  tree_level<4, 36>(sA, sB, sC, sD,
      g_bpr + ((size_t)(3*ROWS + row))*NN + t0,
      g_bpi + ((size_t)(3*ROWS + row))*NN + t0);
  __syncthreads();
  // ---- level 4: d=8, bandpass only ----
  tree_level<8, 0>(sC, sD, nullptr, nullptr,
      g_bpr + ((size_t)(4*ROWS + row))*NN + t0,
      g_bpi + ((size_t)(4*ROWS + row))*NN + t0);
}

// ---------------- kernel 2: gconv + modulus + power + fused /4 downsample ----
// out[n] = sum_{m=0}^{36} g[m] * u[4n + m - 18]
//   where g[m] = sum_{2k+k'=m} H0O[k]*H0O[k']  (two lowpass+decimate stages fused)
// u[t] = ( sqrt(r^2 + i^2)/2^{j/2} + beta )^{sigmoid(root)}
// r[t] = sum_k w[k]*bpr[t + d(k-7)],  i[t] likewise on bpi.
#define TO    256
#define ULEN  (4*TO + 33 + 4)        // 4*256 - 4 + 37 = 1057
#define BPMAX (ULEN + 14*8)          // d=8 worst case = 1169

__global__ __launch_bounds__(256) void scatter_kernel(
    const float* __restrict__ conv_w, const float* __restrict__ roots,
    const float* __restrict__ beta_p, float* __restrict__ out)
{
  __shared__ float s_bpr[BPMAX + 16];
  __shared__ float s_bpi[BPMAX + 16];
  __shared__ float s_u[ULEN + 4];
  __shared__ float s_g[37];
  __shared__ float s_w[QQ * TT];
  __shared__ float s_alpha[QQ];

  const int j   = blockIdx.z;
  const int row = blockIdx.y;          // b*CH + c
  const int b   = row >> 2, c = row & 3;
  const int o0  = blockIdx.x * TO;
  const int d   = (j == 0) ? 1 : (1 << (j - 1));
  const float inv_scale = exp2f(-0.5f * (float)j);
  const float beta = beta_p[0];

  const int tmin  = 4 * o0 - 18;       // first u index needed
  const int pmin  = tmin - 7 * d;      // first bp index needed
  const int bplen = ULEN + 14 * d;

  const float* bpr = g_bpr + ((size_t)(j * ROWS + row)) * NN;
  const float* bpi = g_bpi + ((size_t)(j * ROWS + row)) * NN;

  for (int i = threadIdx.x; i < bplen; i += 256) {
    const int gi = pmin + i;
    const bool in = (gi >= 0 && gi < NN);
    s_bpr[i] = in ? bpr[gi] : 0.f;
    s_bpi[i] = in ? bpi[gi] : 0.f;
  }
  if (threadIdx.x < 37) {              // composite downsample filter
    const int m = threadIdx.x;
    float acc = 0.f;
    for (int k = 0; k < 13; k++) {
      const int kp = m - 2 * k;
      if (kp >= 0 && kp < 13) acc += c_H0O[k] * c_H0O[kp];
    }
    s_g[m] = acc;
  }
  for (int i = threadIdx.x; i < QQ * TT; i += 256) {
    const int q = i / TT, k = i % TT;
    s_w[i] = conv_w[(size_t)(j * CQ + c * QQ + q) * TT + k];
  }
  if (threadIdx.x < QQ) {
    const float rt = roots[j * CQ + c * QQ + threadIdx.x];
    s_alpha[threadIdx.x] = 1.f / (1.f + __expf(-rt));
  }
  __syncthreads();

  for (int q = 0; q < QQ; q++) {
    float w[TT];
#pragma unroll
    for (int k = 0; k < TT; k++) w[k] = s_w[q * TT + k];
    const float alpha = s_alpha[q];

    for (int ui = threadIdx.x; ui < ULEN; ui += 256) {
      const int t = tmin + ui;
      float u = 0.f;
      if (t >= 0 && t < NN) {
        float r = 0.f, im = 0.f;
#pragma unroll
        for (int k = 0; k < TT; k++) {
          r  = fmaf(w[k], s_bpr[ui + d * k], r);
          im = fmaf(w[k], s_bpi[ui + d * k], im);
        }
        const float hyp = sqrtf(fmaf(r, r, im * im)) * inv_scale;
        u = exp2f(alpha * __log2f(hyp + beta));
      }
      s_u[ui] = u;
    }
    __syncthreads();

    float* op = out + ((size_t)(b * OUTCH + j * CQ + c * QQ + q)) * OUTN + o0;
    for (int n = threadIdx.x; n < TO; n += 256) {
      float acc = 0.f;
#pragma unroll
      for (int m = 0; m < 37; m++) acc = fmaf(s_g[m], s_u[4 * n + m], acc);
      op[n] = acc;
    }
    __syncthreads();
  }
}

// ---------------- launch ----------------
extern "C" void kernel_launch(void* const* d_in, const int* in_sizes, int n_in,
                              void* d_out, int out_size)
{
  const float* x      = (const float*)d_in[0];
  const float* conv_w = (const float*)d_in[1];
  const float* roots  = (const float*)d_in[2];
  const float* beta   = (const float*)d_in[3];
  float* out = (float*)d_out;

  dim3 gW(NN / TILE_W, ROWS);          // 32 x 16
  udtcwt_kernel<<<gW, 256>>>(x);

  dim3 gB(OUTN / TO, ROWS, JLEV);      // 64 x 16 x 5
  scatter_kernel<<<gB, 256>>>(conv_w, roots, beta, out);
}